// round 10
// baseline (speedup 1.0000x reference)
#include <cuda_runtime.h>
#include <cstdint>

#define D      1024
#define TPB    256
#define NW     (TPB / 32)
#define FACTOR 4
#define LN_EPS 1e-5f
#define N2     22
#define TILE_F (D + 2 * FACTOR * D)          // 9216 floats / 36KB per row-tile
#define TILE_BYTES (TILE_F * 4)
#define SMEM_BYTES (2 * TILE_BYTES)          // two buffers, 72KB
#define NCTA_PER_SM 3

__device__ __forceinline__ uint32_t smem_u32(const void* p) {
    uint32_t a;
    asm("{ .reg .u64 t; cvta.to.shared.u64 t, %1; cvt.u32.u64 %0, t; }"
        : "=r"(a) : "l"(p));
    return a;
}

__device__ __forceinline__ void cp_bulk(uint32_t dst, const float* src,
                                        uint32_t bytes, uint32_t mb) {
    asm volatile("cp.async.bulk.shared::cta.global.mbarrier::complete_tx::bytes "
                 "[%0], [%1], %2, [%3];"
                 :: "r"(dst), "l"(src), "r"(bytes), "r"(mb) : "memory");
}

__device__ __forceinline__ void issue_row(const float* gq, const float* gk,
                                          const float* gv, size_t r,
                                          float* tile, uint32_t mb) {
    asm volatile("mbarrier.arrive.expect_tx.shared.b64 _, [%0], %1;"
                 :: "r"(mb), "r"((uint32_t)TILE_BYTES) : "memory");
    cp_bulk(smem_u32(tile),            gq + r * D,          D * 4u, mb);
    cp_bulk(smem_u32(tile + D),        gk + r * FACTOR * D, FACTOR * D * 4u, mb);
    cp_bulk(smem_u32(tile + D + FACTOR * D), gv + r * FACTOR * D, FACTOR * D * 4u, mb);
}

__device__ __forceinline__ void mbar_wait(uint32_t mbar, uint32_t parity) {
    uint32_t done;
    do {
        asm volatile(
            "{\n\t.reg .pred p;\n\t"
            "mbarrier.try_wait.parity.acquire.cta.shared::cta.b64 p, [%1], %2, 0x989680;\n\t"
            "selp.b32 %0, 1, 0, p;\n\t}"
            : "=r"(done) : "r"(mbar), "r"(parity) : "memory");
    } while (!done);
}

template <int N>
__device__ __forceinline__ void block_reduce(float* v,
                                             float (*sred)[N2],
                                             float* sbc) {
    const int t    = threadIdx.x;
    const int lane = t & 31;
    const int wid  = t >> 5;
    #pragma unroll
    for (int off = 16; off; off >>= 1)
        #pragma unroll
        for (int i = 0; i < N; i++)
            v[i] += __shfl_xor_sync(0xffffffffu, v[i], off);
    if (lane == 0)
        #pragma unroll
        for (int i = 0; i < N; i++) sred[wid][i] = v[i];
    __syncthreads();
    if (t < N) {
        float s = 0.0f;
        #pragma unroll
        for (int w = 0; w < NW; w++) s += sred[w][t];
        sbc[t] = s;
    }
    __syncthreads();
}

__global__ __launch_bounds__(TPB, NCTA_PER_SM)
void attn_ds_kernel(const float* __restrict__ gq,
                    const float* __restrict__ gk,
                    const float* __restrict__ gv,
                    const float* __restrict__ glw,
                    const float* __restrict__ glb,
                    float* __restrict__ gout,
                    int rows) {
    extern __shared__ float dyn[];          // 2 tile buffers
    __shared__ float sred[NW][N2];
    __shared__ float sbc[N2];
    __shared__ alignas(8) uint64_t mbar[2];

    const int t = threadIdx.x;
    const int stride = gridDim.x;
    const uint32_t mb0 = smem_u32(&mbar[0]);
    const uint32_t mb1 = smem_u32(&mbar[1]);

    if (t == 0) {
        asm volatile("mbarrier.init.shared.b64 [%0], 1;" :: "r"(mb0) : "memory");
        asm volatile("mbarrier.init.shared.b64 [%0], 1;" :: "r"(mb1) : "memory");
        asm volatile("fence.proxy.async.shared::cta;" ::: "memory");
    }
    __syncthreads();

    // w/b: tiny, reused every row -> load once.
    const float4 wv = reinterpret_cast<const float4*>(glw)[t];
    const float4 bv = reinterpret_cast<const float4*>(glb)[t];
    const float we[4] = {wv.x, wv.y, wv.z, wv.w};
    const float be[4] = {bv.x, bv.y, bv.z, bv.w};

    int row = blockIdx.x;
    if (row >= rows) return;

    if (t == 0)
        issue_row(gq, gk, gv, (size_t)row, dyn, mb0);

    int buf = 0;
    uint32_t phase[2] = {0u, 0u};
    const float inv_d = 1.0f / (float)D;

    for (; row < rows; row += stride) {
        const int nbuf = buf ^ 1;
        // All threads finished reading nbuf (two iterations ago) -> safe to refill.
        __syncthreads();
        if (t == 0 && row + stride < rows)
            issue_row(gq, gk, gv, (size_t)(row + stride),
                      dyn + nbuf * TILE_F, nbuf ? mb1 : mb0);

        const uint32_t mbc = buf ? mb1 : mb0;
        mbar_wait(mbc, phase[buf]);
        phase[buf] ^= 1u;

        float* sq = dyn + buf * TILE_F;
        float* sk = sq + D;
        float* sv = sk + FACTOR * D;

        const float4 qv = reinterpret_cast<const float4*>(sq)[t];
        const float qe[4] = {qv.x, qv.y, qv.z, qv.w};

        // ---- q stats ----
        float r2[2];
        r2[0] = qe[0] + qe[1] + qe[2] + qe[3];
        r2[1] = qe[0]*qe[0] + qe[1]*qe[1] + qe[2]*qe[2] + qe[3]*qe[3];
        block_reduce<2>(r2, sred, sbc);
        const float muq = sbc[0] * inv_d;
        const float rsq = rsqrtf(sbc[1] * inv_d - muq * muq + LN_EPS);

        float tq[4];
        float red[N2];
        #pragma unroll
        for (int i = 0; i < N2; i++) red[i] = 0.0f;
        #pragma unroll
        for (int i = 0; i < 4; i++) {
            const float qn = (qe[i] - muq) * rsq * we[i] + be[i];
            tq[i] = qn * we[i];
            red[0] += tq[i];
            red[1] += qn * be[i];
        }

        // slots: 0 C1, 1 C2, 2+f Sk, 6+f Skk, 10+f Dtqk, 14+f Sv, 18+f Svv
        #pragma unroll
        for (int f = 0; f < FACTOR; f++) {
            const float4 kf = reinterpret_cast<const float4*>(sk)[f * TPB + t];
            red[ 2 + f] += kf.x + kf.y + kf.z + kf.w;
            red[ 6 + f] += kf.x*kf.x + kf.y*kf.y + kf.z*kf.z + kf.w*kf.w;
            red[10 + f] += tq[0]*kf.x + tq[1]*kf.y + tq[2]*kf.z + tq[3]*kf.w;
            const float4 vf = reinterpret_cast<const float4*>(sv)[f * TPB + t];
            red[14 + f] += vf.x + vf.y + vf.z + vf.w;
            red[18 + f] += vf.x*vf.x + vf.y*vf.y + vf.z*vf.z + vf.w*vf.w;
        }

        block_reduce<N2>(red, sred, sbc);

        const float C1 = sbc[0];
        const float C2 = sbc[1];

        float acc[4] = {0.0f, 0.0f, 0.0f, 0.0f};
        float accB = 0.0f;

        #pragma unroll
        for (int f = 0; f < FACTOR; f++) {
            const float muk = sbc[2 + f] * inv_d;
            const float rsk = rsqrtf(sbc[6 + f] * inv_d - muk * muk + LN_EPS);
            const float wf  = rsk * (sbc[10 + f] - muk * C1) + C2;

            const float muv = sbc[14 + f] * inv_d;
            const float rsv = rsqrtf(sbc[18 + f] * inv_d - muv * muv + LN_EPS);
            const float wrs = wf * rsv;

            const float4 vf = reinterpret_cast<const float4*>(sv)[f * TPB + t];
            acc[0] += wrs * (vf.x - muv);
            acc[1] += wrs * (vf.y - muv);
            acc[2] += wrs * (vf.z - muv);
            acc[3] += wrs * (vf.w - muv);
            accB += wf;
        }

        float4 o;
        o.x = qe[0] + we[0] * acc[0] + be[0] * accB;
        o.y = qe[1] + we[1] * acc[1] + be[1] * accB;
        o.z = qe[2] + we[2] * acc[2] + be[2] * accB;
        o.w = qe[3] + we[3] * acc[3] + be[3] * accB;
        reinterpret_cast<float4*>(gout + (size_t)row * D)[t] = o;

        buf = nbuf;
    }
}

extern "C" void kernel_launch(void* const* d_in, const int* in_sizes, int n_in,
                              void* d_out, int out_size) {
    const float* q  = (const float*)d_in[0];
    const float* k  = (const float*)d_in[1];
    const float* v  = (const float*)d_in[2];
    const float* lw = (const float*)d_in[3];
    const float* lb = (const float*)d_in[4];
    float* out = (float*)d_out;

    const int rows = out_size / D;                 // B * Sq = 8192
    int grid = 148 * NCTA_PER_SM;                  // persistent CTAs
    if (grid > rows) grid = rows;

    cudaFuncSetAttribute(attn_ds_kernel,
                         cudaFuncAttributeMaxDynamicSharedMemorySize, SMEM_BYTES);
    attn_ds_kernel<<<grid, TPB, SMEM_BYTES>>>(q, k, v, lw, lb, out, rows);
}